// round 15
// baseline (speedup 1.0000x reference)
#include <cuda_runtime.h>
#include <cstdint>
#include <cstddef>

#define T_STEPS 2048
#define BATCH   512
#define HID     33
#define G4      132
#define ODIM    18
#define H1DIM   72
#define NTH     128

// Per-layer outputs y[t][b][k] (t-major). Static device scratch (no allocs).
__device__ float g_y0[(size_t)T_STEPS * BATCH * HID];
__device__ float g_y1[(size_t)T_STEPS * BATCH * HID];

typedef unsigned long long u64;

__device__ __forceinline__ void fma2(u64 &acc, u64 a, u64 b) {
    asm("fma.rn.f32x2 %0, %1, %2, %0;" : "+l"(acc) : "l"(a), "l"(b));
}
__device__ __forceinline__ u64 pack2(float lo, float hi) {
    u64 r; asm("mov.b64 %0, {%1,%2};" : "=l"(r) : "f"(lo), "f"(hi)); return r;
}
__device__ __forceinline__ float2 unpack2(u64 v) {
    float2 r; asm("mov.b64 {%0,%1}, %2;" : "=f"(r.x), "=f"(r.y) : "l"(v)); return r;
}
__device__ __forceinline__ float sigm_(float x) {
    return __fdividef(1.f, 1.f + __expf(-x));
}
__device__ __forceinline__ float tanh_(float x) {
    float e = __expf(2.f * x);
    return 1.f - __fdividef(2.f, e + 1.f);
}

// ---------------------------------------------------------------------------
// One CTA = one batch element. 128 threads = 4 FULL warps (no partial warp).
// Thread j owns fused gate row j (0..127). The 4 leftover rows 128..131
// (o-gates of units 29..32) are k-split across lanes 0/16 of warp (row-128+w):
// every thread runs a 9-pair side chain (zero weights off-lane, uniform issue),
// halves combined with one shfl_xor(16); lane 0 writes the gate.
// Software pipeline: phase A (after B2) = h-chains + activations (x part was
// precomputed); phase B (after B1) = x-chains for step t+1 + cell updates +
// x publish. Phases are balanced, post-barrier bursts halved.
//
// Roles spread across warps: cell for unit u -> thread 4u+1 (u=32 -> thread 3);
// x loader for i -> thread 4i+2 (i=32 -> thread 7).
// ---------------------------------------------------------------------------
template<int IN, bool XBF, int XSRC, int YDST>
__global__ __launch_bounds__(NTH)
void lstm_layer_kernel(const float* __restrict__ xin,
                       const float* __restrict__ Wih,
                       const float* __restrict__ Whh,
                       const float* __restrict__ bih,
                       const float* __restrict__ bhh,
                       float* __restrict__ hid)
{
    constexpr int INP = ((IN + 3) / 4) * 4;   // 12 / 36
    constexpr int NPX = INP / 2;              // 6 / 18 x pairs
    constexpr int NXB = NPX / 2;              // 3 / 9 extra-row half pairs
    const int b = blockIdx.x;
    const int j = threadIdx.x;

    const float* xp = (XSRC == 0) ? g_y0 : (XSRC == 1) ? g_y1 : xin;
    float* yp = (YDST == 0) ? g_y0 : (YDST == 1) ? g_y1 : nullptr;

    __shared__ __align__(16) float h_sh[36];
    __shared__ __align__(16) float x_sh[2][36];
    __shared__ float g_sh[G4];

    // ---- main fused row j (f32x2-packed) ----
    u64 wh_a[18];
#pragma unroll
    for (int p = 0; p < 18; p++) {
        int m = 2 * p;
        float lo = (m     < HID) ? Whh[j * HID + m]     : 0.f;
        float hi = (m + 1 < HID) ? Whh[j * HID + m + 1] : 0.f;
        wh_a[p] = pack2(lo, hi);
    }
    u64 wx_a[NPX];
#pragma unroll
    for (int p = 0; p < NPX; p++) {
        int m = 2 * p;
        float lo = (m     < IN) ? Wih[j * IN + m]     : 0.f;
        float hi = (m + 1 < IN) ? Wih[j * IN + m + 1] : 0.f;
        wx_a[p] = pack2(lo, hi);
    }
    const float bias_a = bih[j] + bhh[j];
    const bool  isg_a  = (j >= 66 && j < 99);   // gate order i,f,g,o

    // ---- extra row rb = 128 + warp, k-half by (j>>4)&1; zero off-lanes ----
    const bool expart = ((j & 15) == 0);        // lanes 0,16 of each warp
    const int  half   = (j >> 4) & 1;
    const int  rb     = 128 + (j >> 5);
    u64 wh_b[9];
#pragma unroll
    for (int p = 0; p < 9; p++) {
        int gp = half * 9 + p, m = 2 * gp;
        float lo = (expart && m     < HID) ? Whh[rb * HID + m]     : 0.f;
        float hi = (expart && m + 1 < HID) ? Whh[rb * HID + m + 1] : 0.f;
        wh_b[p] = pack2(lo, hi);
    }
    u64 wx_b[NXB];
#pragma unroll
    for (int p = 0; p < NXB; p++) {
        int gp = half * NXB + p, m = 2 * gp;
        float lo = (expart && m     < IN) ? Wih[rb * IN + m]     : 0.f;
        float hi = (expart && m + 1 < IN) ? Wih[rb * IN + m + 1] : 0.f;
        wx_b[p] = pack2(lo, hi);
    }
    const float bias_b = bih[rb] + bhh[rb];

    // ---- roles ----
    const bool cellp = ((j & 3) == 1) || (j == 3);
    const int  cu    = (j == 3) ? 32 : (j >> 2);
    bool ldr = false; int li = 0;
    if ((j & 3) == 2 && (j >> 2) < IN && (j >> 2) < 32) { ldr = true; li = j >> 2; }
    if (IN > 32 && j == 7) { ldr = true; li = 32; }

    auto xval = [&](int t, int i) -> float {
        if (XBF) return xp[((size_t)b * T_STEPS + t) * IN + i];
        else     return xp[((size_t)t * BATCH + b) * HID + i];
    };

    // ---- init shared ----
    if (j < 36) { h_sh[j] = 0.f; x_sh[0][j] = 0.f; x_sh[1][j] = 0.f; }
    __syncthreads();
    if (ldr) {
        x_sh[0][li] = xval(0, li);
        x_sh[1][li] = xval(1, li);
    }
    __syncthreads();

    // ---- pre-loop x-contributions for step 0 (from x_sh[0]) ----
    float xc_a, xc_b;
    {
        u64 c0 = 0ull, c1 = 0ull, d0 = 0ull;
        const ulonglong2* xv = (const ulonglong2*)x_sh[0];
        const u64*        xu = (const u64*)x_sh[0];
#pragma unroll
        for (int q = 0; q < NPX / 2; q++) {
            ulonglong2 v = xv[q];
            fma2(c0, wx_a[2 * q],     v.x);
            fma2(c1, wx_a[2 * q + 1], v.y);
        }
#pragma unroll
        for (int p = 0; p < NXB; p++) fma2(d0, wx_b[p], xu[half * NXB + p]);
        float2 e0 = unpack2(c0), e1 = unpack2(c1), e2 = unpack2(d0);
        xc_a = (e0.x + e0.y) + (e1.x + e1.y);
        float xb = e2.x + e2.y;
        xc_b = xb + __shfl_xor_sync(0xFFFFFFFFu, xb, 16);
    }

    float c  = 0.f;
    float xr = ldr ? xval(2, li) : 0.f;   // x(t+2) entering step t

    for (int t = 0; t < T_STEPS; ++t) {
        const int pc = t & 1, pn = pc ^ 1;

        // prefetch x(t+3) (consumed next step's publish)
        float xr2 = 0.f;
        if (ldr && (t + 3) < T_STEPS) xr2 = xval(t + 3, li);

        // ---- phase A: h-chains + activations ----
        u64 a0 = 0ull, a1 = 0ull, bh = 0ull;
        {
            const ulonglong2* hv = (const ulonglong2*)h_sh;
            const u64*        hu = (const u64*)h_sh;
#pragma unroll
            for (int q = 0; q < 9; q++) {
                ulonglong2 v = hv[q];                 // LDS.128 broadcast
                fma2(a0, wh_a[2 * q],     v.x);
                fma2(a1, wh_a[2 * q + 1], v.y);
            }
#pragma unroll
            for (int p = 0; p < 9; p++) fma2(bh, wh_b[p], hu[half * 9 + p]);
        }
        {
            float2 e0 = unpack2(a0), e1 = unpack2(a1);
            float pre_a = (e0.x + e0.y) + (e1.x + e1.y) + xc_a + bias_a;
            g_sh[j] = isg_a ? tanh_(pre_a) : sigm_(pre_a);
        }
        {
            float2 e2 = unpack2(bh);
            float hb = e2.x + e2.y;
            hb += __shfl_xor_sync(0xFFFFFFFFu, hb, 16);
            if ((j & 31) == 0)                        // lane 0 owns the write
                g_sh[rb] = sigm_(hb + xc_b + bias_b); // rows 128..131 are o-gates
        }
        __syncthreads();   // B1: gates visible; h/x reads of this step done

        // ---- phase B: x-chains for step t+1 + cell update + x publish ----
        u64 c0 = 0ull, c1 = 0ull, d0 = 0ull;
        {
            const ulonglong2* xv = (const ulonglong2*)x_sh[pn];   // holds x_{t+1}
            const u64*        xu = (const u64*)x_sh[pn];
#pragma unroll
            for (int q = 0; q < NPX / 2; q++) {
                ulonglong2 v = xv[q];
                fma2(c0, wx_a[2 * q],     v.x);
                fma2(c1, wx_a[2 * q + 1], v.y);
            }
#pragma unroll
            for (int p = 0; p < NXB; p++) fma2(d0, wx_b[p], xu[half * NXB + p]);
        }
        {
            float2 f0 = unpack2(c0), f1 = unpack2(c1), f2 = unpack2(d0);
            xc_a = (f0.x + f0.y) + (f1.x + f1.y);
            float xb = f2.x + f2.y;
            xc_b = xb + __shfl_xor_sync(0xFFFFFFFFu, xb, 16);
        }

        if (cellp) {
            float gi = g_sh[cu];
            float gf = g_sh[cu + 33];
            float gg = g_sh[cu + 66];
            float go = g_sh[cu + 99];
            c = gf * c + gi * gg;
            float h = go * tanh_(c);
            h_sh[cu] = h;
            if (YDST >= 0) yp[((size_t)t * BATCH + b) * HID + cu] = h;
            if (t == T_STEPS - 1) hid[b * HID + cu] = h;
        } else if (ldr) {
            x_sh[pc][li] = xr;    // publish x(t+2)
            xr = xr2;
        }
        __syncthreads();   // B2: h_t and x_{t+2} visible; pn reads done
    }
}

// ---------------------------------------------------------------------------
// MLP head: out = GELU(hid@W1^T + b1) @ W2^T + b2, one block per row.
// ---------------------------------------------------------------------------
__global__ __launch_bounds__(H1DIM)
void head_kernel(const float* __restrict__ hid,
                 const float* __restrict__ W1, const float* __restrict__ b1,
                 const float* __restrict__ W2, const float* __restrict__ b2,
                 float* __restrict__ out)
{
    const int rr = blockIdx.x;
    const int u  = threadIdx.x;
    __shared__ float hrow[HID];
    __shared__ float h1[H1DIM];

    if (u < HID) hrow[u] = hid[rr * HID + u];
    __syncthreads();

    float s = b1[u];
#pragma unroll
    for (int m = 0; m < HID; m++) s += W1[u * HID + m] * hrow[m];
    h1[u] = 0.5f * s * (1.f + erff(s * 0.70710678118654752f));  // exact GELU
    __syncthreads();

    if (u < ODIM) {
        float s2 = b2[u];
#pragma unroll
        for (int m = 0; m < H1DIM; m++) s2 += W2[u * H1DIM + m] * h1[m];
        out[rr * ODIM + u] = s2;
    }
}

extern "C" void kernel_launch(void* const* d_in, const int* in_sizes, int n_in,
                              void* d_out, int out_size)
{
    const float* x    = (const float*)d_in[0];
    const float* Wih0 = (const float*)d_in[1];
    const float* Whh0 = (const float*)d_in[2];
    const float* bih0 = (const float*)d_in[3];
    const float* bhh0 = (const float*)d_in[4];
    const float* Wih1 = (const float*)d_in[5];
    const float* Whh1 = (const float*)d_in[6];
    const float* bih1 = (const float*)d_in[7];
    const float* bhh1 = (const float*)d_in[8];
    const float* Wih2 = (const float*)d_in[9];
    const float* Whh2 = (const float*)d_in[10];
    const float* bih2 = (const float*)d_in[11];
    const float* bhh2 = (const float*)d_in[12];
    const float* W1   = (const float*)d_in[13];
    const float* b1   = (const float*)d_in[14];
    const float* W2   = (const float*)d_in[15];
    const float* b2   = (const float*)d_in[16];

    float* out = (float*)d_out;                      // [3, 512, 18]
    float* hid = out + 3 * BATCH * ODIM;             // [3, 512, 33]

    lstm_layer_kernel<11, true,  -1, 0><<<BATCH, NTH>>>(
        x, Wih0, Whh0, bih0, bhh0, hid);
    lstm_layer_kernel<33, false,  0, 1><<<BATCH, NTH>>>(
        nullptr, Wih1, Whh1, bih1, bhh1, hid + BATCH * HID);
    lstm_layer_kernel<33, false,  1, -1><<<BATCH, NTH>>>(
        nullptr, Wih2, Whh2, bih2, bhh2, hid + 2 * BATCH * HID);
    head_kernel<<<3 * BATCH, H1DIM>>>(hid, W1, b1, W2, b2, out);
}

// round 16
// speedup vs baseline: 2.0538x; 2.0538x over previous
#include <cuda_runtime.h>
#include <cstdint>
#include <cstddef>

#define T_STEPS 2048
#define BATCH   512
#define HID     33
#define G4      132
#define ODIM    18
#define H1DIM   72
#define NE      4              // batch elements per CTA
#define NTH     (G4 * NE)      // 528 threads

// Per-layer outputs y[t][b][k] (t-major). Static device scratch (no allocs).
__device__ float g_y0[(size_t)T_STEPS * BATCH * HID];
__device__ float g_y1[(size_t)T_STEPS * BATCH * HID];

typedef unsigned long long u64;

__device__ __forceinline__ void fma2(u64 &acc, u64 a, u64 b) {
    asm("fma.rn.f32x2 %0, %1, %2, %0;" : "+l"(acc) : "l"(a), "l"(b));
}
__device__ __forceinline__ u64 pack2(float lo, float hi) {
    u64 r; asm("mov.b64 %0, {%1,%2};" : "=l"(r) : "f"(lo), "f"(hi)); return r;
}
__device__ __forceinline__ float2 unpack2(u64 v) {
    float2 r; asm("mov.b64 {%0,%1}, %2;" : "=f"(r.x), "=f"(r.y) : "l"(v)); return r;
}
__device__ __forceinline__ float sigm_(float x) {
    return __fdividef(1.f, 1.f + __expf(-x));
}
__device__ __forceinline__ float tanh_(float x) {
    float e = __expf(2.f * x);
    return 1.f - __fdividef(2.f, e + 1.f);
}

// ---------------------------------------------------------------------------
// One CTA = NE(=4) batch elements, co-scheduled. Thread (e, j) executes
// EXACTLY the R5 per-thread program for element e, gate row j: register-
// resident f32x2 weights, two shared broadcast chains (h, x), two barriers
// per step. The barriers and the dependent path are amortized over 4
// elements, and the ~16 warps between barriers hide LDS/MUFU latency.
// Per-element arithmetic identical to R5 -> identical numerics.
//
// IN:   input width (11 for layer 0, 33 otherwise)
// XBF:  x layout [B,T,IN] (layer 0) vs [T,B,HID] (y buffers)
// XSRC: -1 = xin param, 0 = g_y0, 1 = g_y1
// YDST: -1 = no per-step output, 0 = g_y0, 1 = g_y1
// ---------------------------------------------------------------------------
template<int IN, bool XBF, int XSRC, int YDST>
__global__ __launch_bounds__(NTH, 1)
void lstm_layer_kernel(const float* __restrict__ xin,
                       const float* __restrict__ Wih,
                       const float* __restrict__ Whh,
                       const float* __restrict__ bih,
                       const float* __restrict__ bhh,
                       float* __restrict__ hid)
{
    constexpr int INP = ((IN + 3) / 4) * 4;   // 12 / 36
    constexpr int NPI = INP / 2;
    const int tid = threadIdx.x;
    const int e   = tid / G4;          // element slot 0..3
    const int j   = tid % G4;          // fused gate row 0..131
    const int b   = blockIdx.x * NE + e;

    const float* xp = (XSRC == 0) ? g_y0 : (XSRC == 1) ? g_y1 : xin;
    float* yp = (YDST == 0) ? g_y0 : (YDST == 1) ? g_y1 : nullptr;

    __shared__ __align__(16) float h_sh[NE][2][36];   // double-buffered h
    __shared__ __align__(16) float x_sh[NE][36];      // single-buffered x (phase-split safe)
    __shared__ float g_sh[NE][G4];

    // ---- pack weights into f32x2 registers (identical to R5) ----
    u64 whh2[18];
#pragma unroll
    for (int p = 0; p < 18; p++) {
        int m = 2 * p;
        float lo = (m     < HID) ? Whh[j * HID + m]     : 0.f;
        float hi = (m + 1 < HID) ? Whh[j * HID + m + 1] : 0.f;
        whh2[p] = pack2(lo, hi);
    }
    u64 wih2[NPI];
#pragma unroll
    for (int p = 0; p < NPI; p++) {
        int m = 2 * p;
        float lo = (m     < IN) ? Wih[j * IN + m]     : 0.f;
        float hi = (m + 1 < IN) ? Wih[j * IN + m + 1] : 0.f;
        wih2[p] = pack2(lo, hi);
    }
    const float bias = bih[j] + bhh[j];
    const bool is_g  = (j >= 66 && j < 99);        // PyTorch gate order i,f,g,o

    const bool ldr = (j >= 64) && (j < 64 + IN);   // x loader threads (per element)
    const int  li  = j - 64;

    auto xval = [&](int t, int i) -> float {
        if (XBF) return xp[((size_t)b * T_STEPS + t) * IN + i];
        else     return xp[((size_t)t * BATCH + b) * HID + i];
    };

    // ---- init shared state (both parities zero; pads stay zero) ----
    for (int i = tid; i < NE * 2 * 36; i += NTH) (&h_sh[0][0][0])[i] = 0.f;
    for (int i = tid; i < NE * 36;     i += NTH) (&x_sh[0][0])[i]    = 0.f;
    __syncthreads();
    if (ldr) x_sh[e][li] = xval(0, li);
    __syncthreads();

    float c  = 0.f;                       // cell state (threads j<33)
    float xr = ldr ? xval(1, li) : 0.f;   // x(t+1) entering step t

    for (int t = 0; t < T_STEPS; ++t) {
        const int pc = t & 1, pn = pc ^ 1;

        // depth-2 x prefetch (long-scoreboard hidden across steps)
        float xr2 = 0.f;
        if (ldr && (t + 2) < T_STEPS) xr2 = xval(t + 2, li);

        // gates[j] = bias + Whh[j]·h + Wih[j]·x_t  (two independent f32x2 chains)
        u64 acch = 0ull, accx = 0ull;
        const ulonglong2* hv = (const ulonglong2*)h_sh[e][pc];
        const ulonglong2* xv = (const ulonglong2*)x_sh[e];
#pragma unroll
        for (int q = 0; q < 9; q++) {
            ulonglong2 v = hv[q];                 // one LDS.128 -> two packed operands
            fma2(acch, whh2[2 * q],     v.x);
            fma2(acch, whh2[2 * q + 1], v.y);
        }
#pragma unroll
        for (int q = 0; q < INP / 4; q++) {
            ulonglong2 v = xv[q];
            fma2(accx, wih2[2 * q],     v.x);
            fma2(accx, wih2[2 * q + 1], v.y);
        }
        float2 ah = unpack2(acch);
        float2 ax = unpack2(accx);
        float pre = (ah.x + ah.y) + (ax.x + ax.y) + bias;
        float act = is_g ? tanh_(pre) : sigm_(pre);
        g_sh[e][j] = act;
        __syncthreads();   // B1: gates visible; all h_sh/x_sh reads complete

        if (j < HID) {
            float gi = g_sh[e][j];
            float gf = g_sh[e][j + 33];
            float gg = g_sh[e][j + 66];
            float go = g_sh[e][j + 99];
            c = gf * c + gi * gg;
            float h = go * tanh_(c);
            h_sh[e][pn][j] = h;
            if (YDST >= 0) yp[((size_t)t * BATCH + b) * HID + j] = h;
            if (t == T_STEPS - 1) hid[b * HID + j] = h;
        } else if (ldr) {
            x_sh[e][li] = xr;    // publish x(t+1)
            xr = xr2;
        }
        __syncthreads();   // B2: h_t, x_{t+1} ready
    }
}

// ---------------------------------------------------------------------------
// MLP head: out = GELU(hid@W1^T + b1) @ W2^T + b2, one block per row.
// ---------------------------------------------------------------------------
__global__ __launch_bounds__(H1DIM)
void head_kernel(const float* __restrict__ hid,
                 const float* __restrict__ W1, const float* __restrict__ b1,
                 const float* __restrict__ W2, const float* __restrict__ b2,
                 float* __restrict__ out)
{
    const int rr = blockIdx.x;
    const int u  = threadIdx.x;
    __shared__ float hrow[HID];
    __shared__ float h1[H1DIM];

    if (u < HID) hrow[u] = hid[rr * HID + u];
    __syncthreads();

    float s = b1[u];
#pragma unroll
    for (int m = 0; m < HID; m++) s += W1[u * HID + m] * hrow[m];
    h1[u] = 0.5f * s * (1.f + erff(s * 0.70710678118654752f));  // exact GELU
    __syncthreads();

    if (u < ODIM) {
        float s2 = b2[u];
#pragma unroll
        for (int m = 0; m < H1DIM; m++) s2 += W2[u * H1DIM + m] * h1[m];
        out[rr * ODIM + u] = s2;
    }
}

extern "C" void kernel_launch(void* const* d_in, const int* in_sizes, int n_in,
                              void* d_out, int out_size)
{
    const float* x    = (const float*)d_in[0];
    const float* Wih0 = (const float*)d_in[1];
    const float* Whh0 = (const float*)d_in[2];
    const float* bih0 = (const float*)d_in[3];
    const float* bhh0 = (const float*)d_in[4];
    const float* Wih1 = (const float*)d_in[5];
    const float* Whh1 = (const float*)d_in[6];
    const float* bih1 = (const float*)d_in[7];
    const float* bhh1 = (const float*)d_in[8];
    const float* Wih2 = (const float*)d_in[9];
    const float* Whh2 = (const float*)d_in[10];
    const float* bih2 = (const float*)d_in[11];
    const float* bhh2 = (const float*)d_in[12];
    const float* W1   = (const float*)d_in[13];
    const float* b1   = (const float*)d_in[14];
    const float* W2   = (const float*)d_in[15];
    const float* b2   = (const float*)d_in[16];

    float* out = (float*)d_out;                      // [3, 512, 18]
    float* hid = out + 3 * BATCH * ODIM;             // [3, 512, 33]

    const int grid = BATCH / NE;   // 128

    lstm_layer_kernel<11, true,  -1, 0><<<grid, NTH>>>(
        x, Wih0, Whh0, bih0, bhh0, hid);
    lstm_layer_kernel<33, false,  0, 1><<<grid, NTH>>>(
        nullptr, Wih1, Whh1, bih1, bhh1, hid + BATCH * HID);
    lstm_layer_kernel<33, false,  1, -1><<<grid, NTH>>>(
        nullptr, Wih2, Whh2, bih2, bhh2, hid + 2 * BATCH * HID);
    head_kernel<<<3 * BATCH, H1DIM>>>(hid, W1, b1, W2, b2, out);
}